// round 2
// baseline (speedup 1.0000x reference)
#include <cuda_runtime.h>

// ---------------------------------------------------------------------------
// QNNClassifier fused single-kernel version.
//
//   ev = (1, cos x0, sin x0)^T K (1, cos x1, sin x1)
//
// K (9 coefficients, fc_w/fc_b folded in) depends only on q_params; thread 0
// of each block recomputes it into smem while the block's global loads (issued
// first) are in flight. One kernel, one graph node.
// ---------------------------------------------------------------------------

struct Cx { float re, im; };
__device__ __forceinline__ Cx cmul(Cx a, Cx b) {
    return { a.re * b.re - a.im * b.im, a.re * b.im + a.im * b.re };
}
__device__ __forceinline__ Cx cadd(Cx a, Cx b) { return { a.re + b.re, a.im + b.im }; }

__device__ __forceinline__ void compute_K(const float* __restrict__ qp,
                                          const float* __restrict__ fc_w,
                                          const float* __restrict__ fc_b,
                                          float* sK) {
    Cx U[4][4];
    #pragma unroll
    for (int i = 0; i < 4; i++)
        #pragma unroll
        for (int j = 0; j < 4; j++)
            U[i][j] = { (i == j) ? 1.f : 0.f, 0.f };

    #pragma unroll
    for (int l = 0; l < 2; l++) {
        Cx r[2][2][2];
        #pragma unroll
        for (int w = 0; w < 2; w++) {
            float phi   = qp[(l * 2 + w) * 3 + 0];
            float theta = qp[(l * 2 + w) * 3 + 1];
            float omega = qp[(l * 2 + w) * 3 + 2];
            float c, s;
            __sincosf(0.5f * theta, &s, &c);
            float sp, cp, sm, cm;
            __sincosf(-0.5f * (phi + omega), &sp, &cp);   // ep = exp(-i(phi+omega)/2)
            __sincosf( 0.5f * (phi - omega), &sm, &cm);   // em = exp( i(phi-omega)/2)
            Cx ep = { cp, sp }, em = { cm, sm };
            r[w][0][0] = { ep.re * c, ep.im * c };
            r[w][0][1] = { -em.re * s, -em.im * s };
            r[w][1][0] = { em.re * s, -em.im * s };       // conj(em)*s
            r[w][1][1] = { ep.re * c, -ep.im * c };       // conj(ep)*c
        }
        Cx G[4][4];
        #pragma unroll
        for (int a = 0; a < 2; a++)
            #pragma unroll
            for (int b = 0; b < 2; b++)
                #pragma unroll
                for (int c2 = 0; c2 < 2; c2++)
                    #pragma unroll
                    for (int d = 0; d < 2; d++)
                        G[2 * a + b][2 * c2 + d] = cmul(r[0][a][c2], r[1][b][d]);
        Cx T[4][4];
        #pragma unroll
        for (int i = 0; i < 4; i++)
            #pragma unroll
            for (int j = 0; j < 4; j++) {
                Cx acc = { 0.f, 0.f };
                #pragma unroll
                for (int k = 0; k < 4; k++) acc = cadd(acc, cmul(G[i][k], U[k][j]));
                T[i][j] = acc;
            }
        // CNOT01 then CNOT10: net row permutation new = (T0, T2, T3, T1)
        #pragma unroll
        for (int j = 0; j < 4; j++) {
            U[0][j] = T[0][j];
            U[1][j] = T[2][j];
            U[2][j] = T[3][j];
            U[3][j] = T[1][j];
        }
    }

    float wgt = fc_w[0];
    float A[4][4];
    #pragma unroll
    for (int i = 0; i < 4; i++)
        #pragma unroll
        for (int j = 0; j < 4; j++) {
            float acc = 0.f;
            #pragma unroll
            for (int k = 0; k < 4; k++) {
                float zk = (k < 2) ? 1.f : -1.f;
                acc += zk * (U[k][i].re * U[k][j].re + U[k][i].im * U[k][j].im);
            }
            A[i][j] = wgt * acc;
        }

    sK[0] = 0.25f * (A[0][0] + A[1][1] + A[2][2] + A[3][3]) + fc_b[0];
    sK[1] = 0.25f * (A[0][0] - A[1][1] + A[2][2] - A[3][3]);   // C1
    sK[2] = 0.50f * (A[0][1] + A[2][3]);                       // S1
    sK[3] = 0.25f * (A[0][0] + A[1][1] - A[2][2] - A[3][3]);   // C0
    sK[4] = 0.25f * (A[0][0] - A[1][1] - A[2][2] + A[3][3]);   // C0C1
    sK[5] = 0.50f * (A[0][1] - A[2][3]);                       // C0S1
    sK[6] = 0.50f * (A[0][2] + A[1][3]);                       // S0
    sK[7] = 0.50f * (A[0][2] - A[1][3]);                       // S0C1
    sK[8] = 0.50f * (A[0][3] + A[1][2]);                       // S0S1
}

// 8 samples per thread: 4 input float4, 2 output float4.
__global__ void __launch_bounds__(256)
qnn_fused_kernel(const float* __restrict__ qp,
                 const float* __restrict__ fc_w,
                 const float* __restrict__ fc_b,
                 const float4* __restrict__ x4,
                 float4* __restrict__ out4) {
    __shared__ float sK[9];
    unsigned t = blockIdx.x * 256u + threadIdx.x;

    // Front-batch all global loads so they are in flight while thread 0
    // computes the batch-shared coefficients.
    float4 xv0 = __ldcs(&x4[4u * t + 0]);
    float4 xv1 = __ldcs(&x4[4u * t + 1]);
    float4 xv2 = __ldcs(&x4[4u * t + 2]);
    float4 xv3 = __ldcs(&x4[4u * t + 3]);

    if (threadIdx.x == 0) {
        compute_K(qp, fc_w, fc_b, sK);
    }
    __syncthreads();

    float k00 = sK[0], k01 = sK[1], k02 = sK[2];
    float k10 = sK[3], k11 = sK[4], k12 = sK[5];
    float k20 = sK[6], k21 = sK[7], k22 = sK[8];

    float xs[16] = { xv0.x, xv0.y, xv0.z, xv0.w,
                     xv1.x, xv1.y, xv1.z, xv1.w,
                     xv2.x, xv2.y, xv2.z, xv2.w,
                     xv3.x, xv3.y, xv3.z, xv3.w };

    float res[8];
    #pragma unroll
    for (int s = 0; s < 8; s++) {
        float C0, S0, C1, S1;
        __sincosf(xs[2 * s + 0], &S0, &C0);
        __sincosf(xs[2 * s + 1], &S1, &C1);
        float row0 = k00 + k01 * C1 + k02 * S1;
        float row1 = k10 + k11 * C1 + k12 * S1;
        float row2 = k20 + k21 * C1 + k22 * S1;
        res[s] = row0 + C0 * row1 + S0 * row2;
    }

    __stcs(&out4[2u * t + 0], make_float4(res[0], res[1], res[2], res[3]));
    __stcs(&out4[2u * t + 1], make_float4(res[4], res[5], res[6], res[7]));
}

extern "C" void kernel_launch(void* const* d_in, const int* in_sizes, int n_in,
                              void* d_out, int out_size) {
    const float* x    = (const float*)d_in[0];   // [B, 2]
    const float* qp   = (const float*)d_in[1];   // [2, 2, 3]
    const float* fc_w = (const float*)d_in[2];   // [1, 1]
    const float* fc_b = (const float*)d_in[3];   // [1]

    // out_size = B. 8 samples per thread, 256 threads per block.
    int threads = 256;
    int blocks = (out_size + threads * 8 - 1) / (threads * 8);   // 1024 for B=2M
    qnn_fused_kernel<<<blocks, threads>>>(qp, fc_w, fc_b,
                                          (const float4*)x, (float4*)d_out);
    (void)n_in; (void)in_sizes;
}

// round 3
// speedup vs baseline: 1.0025x; 1.0025x over previous
#include <cuda_runtime.h>

// ---------------------------------------------------------------------------
// QNNClassifier fused single-kernel, register-controlled.
//
//   ev = (1, cos x0, sin x0)^T K (1, cos x1, sin x1)
//
// K (9 coefficients, fc_w/fc_b folded in) depends only on q_params. Thread 0
// of each block recomputes it (__noinline__, spills under the launch_bounds
// cap — harmless) while the block's front-batched global loads are in flight.
// Main path keeps R1's 4-samples/thread 32-reg shape.
// ---------------------------------------------------------------------------

struct Cx { float re, im; };
__device__ __forceinline__ Cx cmul(Cx a, Cx b) {
    return { a.re * b.re - a.im * b.im, a.re * b.im + a.im * b.re };
}
__device__ __forceinline__ Cx cadd(Cx a, Cx b) { return { a.re + b.re, a.im + b.im }; }

__device__ __noinline__ void compute_K(const float* __restrict__ qp,
                                       const float* __restrict__ fc_w,
                                       const float* __restrict__ fc_b,
                                       float* sK) {
    Cx U[4][4];
    #pragma unroll
    for (int i = 0; i < 4; i++)
        #pragma unroll
        for (int j = 0; j < 4; j++)
            U[i][j] = { (i == j) ? 1.f : 0.f, 0.f };

    for (int l = 0; l < 2; l++) {
        Cx r[2][2][2];
        for (int w = 0; w < 2; w++) {
            float phi   = qp[(l * 2 + w) * 3 + 0];
            float theta = qp[(l * 2 + w) * 3 + 1];
            float omega = qp[(l * 2 + w) * 3 + 2];
            float c, s;
            __sincosf(0.5f * theta, &s, &c);
            float sp, cp, sm, cm;
            __sincosf(-0.5f * (phi + omega), &sp, &cp);   // ep = exp(-i(phi+omega)/2)
            __sincosf( 0.5f * (phi - omega), &sm, &cm);   // em = exp( i(phi-omega)/2)
            Cx ep = { cp, sp }, em = { cm, sm };
            r[w][0][0] = { ep.re * c, ep.im * c };
            r[w][0][1] = { -em.re * s, -em.im * s };
            r[w][1][0] = { em.re * s, -em.im * s };       // conj(em)*s
            r[w][1][1] = { ep.re * c, -ep.im * c };       // conj(ep)*c
        }
        Cx G[4][4];
        for (int a = 0; a < 2; a++)
            for (int b = 0; b < 2; b++)
                for (int c2 = 0; c2 < 2; c2++)
                    for (int d = 0; d < 2; d++)
                        G[2 * a + b][2 * c2 + d] = cmul(r[0][a][c2], r[1][b][d]);
        Cx T[4][4];
        for (int i = 0; i < 4; i++)
            for (int j = 0; j < 4; j++) {
                Cx acc = { 0.f, 0.f };
                for (int k = 0; k < 4; k++) acc = cadd(acc, cmul(G[i][k], U[k][j]));
                T[i][j] = acc;
            }
        // CNOT01 then CNOT10: net row permutation new = (T0, T2, T3, T1)
        for (int j = 0; j < 4; j++) {
            U[0][j] = T[0][j];
            U[1][j] = T[2][j];
            U[2][j] = T[3][j];
            U[3][j] = T[1][j];
        }
    }

    float wgt = fc_w[0];
    float A[4][4];
    for (int i = 0; i < 4; i++)
        for (int j = 0; j < 4; j++) {
            float acc = 0.f;
            for (int k = 0; k < 4; k++) {
                float zk = (k < 2) ? 1.f : -1.f;
                acc += zk * (U[k][i].re * U[k][j].re + U[k][i].im * U[k][j].im);
            }
            A[i][j] = wgt * acc;
        }

    sK[0] = 0.25f * (A[0][0] + A[1][1] + A[2][2] + A[3][3]) + fc_b[0];
    sK[1] = 0.25f * (A[0][0] - A[1][1] + A[2][2] - A[3][3]);   // C1
    sK[2] = 0.50f * (A[0][1] + A[2][3]);                       // S1
    sK[3] = 0.25f * (A[0][0] + A[1][1] - A[2][2] - A[3][3]);   // C0
    sK[4] = 0.25f * (A[0][0] - A[1][1] - A[2][2] + A[3][3]);   // C0C1
    sK[5] = 0.50f * (A[0][1] - A[2][3]);                       // C0S1
    sK[6] = 0.50f * (A[0][2] + A[1][3]);                       // S0
    sK[7] = 0.50f * (A[0][2] - A[1][3]);                       // S0C1
    sK[8] = 0.50f * (A[0][3] + A[1][2]);                       // S0S1
}

// 4 samples per thread: 2 input float4, 1 output float4. (R1's 32-reg shape.)
__global__ void __launch_bounds__(256, 6)
qnn_fused_kernel(const float* __restrict__ qp,
                 const float* __restrict__ fc_w,
                 const float* __restrict__ fc_b,
                 const float4* __restrict__ x4,
                 float4* __restrict__ out4) {
    __shared__ float sK[9];
    unsigned t = blockIdx.x * 256u + threadIdx.x;

    // Front-batch loads so they are in flight while thread 0 builds K.
    float4 xa = __ldcs(&x4[2u * t + 0]);
    float4 xb = __ldcs(&x4[2u * t + 1]);

    if (threadIdx.x == 0) {
        compute_K(qp, fc_w, fc_b, sK);
    }
    __syncthreads();

    float k00 = sK[0], k01 = sK[1], k02 = sK[2];
    float k10 = sK[3], k11 = sK[4], k12 = sK[5];
    float k20 = sK[6], k21 = sK[7], k22 = sK[8];

    float xs[8] = { xa.x, xa.y, xa.z, xa.w, xb.x, xb.y, xb.z, xb.w };

    float res[4];
    #pragma unroll
    for (int s = 0; s < 4; s++) {
        float C0, S0, C1, S1;
        __sincosf(xs[2 * s + 0], &S0, &C0);
        __sincosf(xs[2 * s + 1], &S1, &C1);
        float row0 = k00 + k01 * C1 + k02 * S1;
        float row1 = k10 + k11 * C1 + k12 * S1;
        float row2 = k20 + k21 * C1 + k22 * S1;
        res[s] = row0 + C0 * row1 + S0 * row2;
    }

    __stcs(&out4[t], make_float4(res[0], res[1], res[2], res[3]));
}

extern "C" void kernel_launch(void* const* d_in, const int* in_sizes, int n_in,
                              void* d_out, int out_size) {
    const float* x    = (const float*)d_in[0];   // [B, 2]
    const float* qp   = (const float*)d_in[1];   // [2, 2, 3]
    const float* fc_w = (const float*)d_in[2];   // [1, 1]
    const float* fc_b = (const float*)d_in[3];   // [1]

    // out_size = B. 4 samples per thread, 256 threads per block.
    int threads = 256;
    int blocks = (out_size + threads * 4 - 1) / (threads * 4);   // 2048 for B=2M
    qnn_fused_kernel<<<blocks, threads>>>(qp, fc_w, fc_b,
                                          (const float4*)x, (float4*)d_out);
    (void)n_in; (void)in_sizes;
}

// round 4
// speedup vs baseline: 1.2216x; 1.2186x over previous
#include <cuda_runtime.h>

// ---------------------------------------------------------------------------
// QNNClassifier fused single-kernel, warp-parallel coefficient computation.
//
//   ev = (1, cos x0, sin x0)^T K (1, cos x1, sin x1)
//
// K (9 coefficients, fc_w/fc_b folded) depends only on q_params. Warp 0 of
// each block computes it in ~500 cycles (one complex U element per lane,
// shfl-based 4x4 complex matmuls), fully hidden under the block's
// front-batched DRAM loads. Main path: 8 samples/thread, single wave.
// ---------------------------------------------------------------------------

struct Cx { float re, im; };
__device__ __forceinline__ Cx cmul(Cx a, Cx b) {
    return { a.re * b.re - a.im * b.im, a.re * b.im + a.im * b.re };
}

// Warp-collective: all 32 lanes of warp 0 execute this. Lane L owns U[i][j],
// i = (L>>2)&3, j = L&3 (lanes 16-31 mirror lanes 0-15).
__device__ __forceinline__ void warp_compute_K(const float* __restrict__ qp,
                                               const float* __restrict__ fc_w,
                                               const float* __restrict__ fc_b,
                                               float* sA, float* sK) {
    const unsigned FULL = 0xffffffffu;
    int L = threadIdx.x;
    int i = (L >> 2) & 3, j = L & 3;
    int a = (i >> 1) & 1, b = i & 1;

    float ur = (i == j) ? 1.f : 0.f, ui = 0.f;

    #pragma unroll
    for (int l = 0; l < 2; l++) {
        // Rot matrices for both wires (computed redundantly by every lane).
        float ph0 = qp[l * 6 + 0], th0 = qp[l * 6 + 1], om0 = qp[l * 6 + 2];
        float ph1 = qp[l * 6 + 3], th1 = qp[l * 6 + 4], om1 = qp[l * 6 + 5];

        float s0, c0; __sincosf(0.5f * th0, &s0, &c0);
        float sp0, cp0, sm0, cm0;
        __sincosf(-0.5f * (ph0 + om0), &sp0, &cp0);   // ep0
        __sincosf( 0.5f * (ph0 - om0), &sm0, &cm0);   // em0
        Cx r0_00 = {  cp0 * c0,  sp0 * c0 };
        Cx r0_01 = { -cm0 * s0, -sm0 * s0 };
        Cx r0_10 = {  cm0 * s0, -sm0 * s0 };
        Cx r0_11 = {  cp0 * c0, -sp0 * c0 };

        float s1, c1; __sincosf(0.5f * th1, &s1, &c1);
        float sp1, cp1, sm1, cm1;
        __sincosf(-0.5f * (ph1 + om1), &sp1, &cp1);
        __sincosf( 0.5f * (ph1 - om1), &sm1, &cm1);
        Cx r1_00 = {  cp1 * c1,  sp1 * c1 };
        Cx r1_01 = { -cm1 * s1, -sm1 * s1 };
        Cx r1_10 = {  cm1 * s1, -sm1 * s1 };
        Cx r1_11 = {  cp1 * c1, -sp1 * c1 };

        // This lane's rows of r0 (row a) and r1 (row b).
        Cx r0c0 = a ? r0_10 : r0_00;   // r0[a][0]
        Cx r0c1 = a ? r0_11 : r0_01;   // r0[a][1]
        Cx r1d0 = b ? r1_10 : r1_00;   // r1[b][0]
        Cx r1d1 = b ? r1_11 : r1_01;   // r1[b][1]

        // T[i][j] = sum_k kron(r0,r1)[i][k] * U[k][j]
        Cx T = { 0.f, 0.f };
        #pragma unroll
        for (int k = 0; k < 4; k++) {
            Cx g = cmul((k & 2) ? r0c1 : r0c0, (k & 1) ? r1d1 : r1d0);
            float wre = __shfl_sync(FULL, ur, 4 * k + j);
            float wim = __shfl_sync(FULL, ui, 4 * k + j);
            T.re += g.re * wre - g.im * wim;
            T.im += g.re * wim + g.im * wre;
        }
        // CNOT01 then CNOT10: row permutation new[i] = T[perm[i]], perm={0,2,3,1}
        int pi = (0x78 >> (2 * i)) & 3;
        ur = __shfl_sync(FULL, T.re, 4 * pi + j);
        ui = __shfl_sync(FULL, T.im, 4 * pi + j);
    }

    // A[i][j] = fc_w * Re( sum_k z_k conj(U[k][i]) U[k][j] ), z=(1,1,-1,-1)
    float acc = 0.f;
    #pragma unroll
    for (int k = 0; k < 4; k++) {
        float ire = __shfl_sync(FULL, ur, 4 * k + i);
        float iim = __shfl_sync(FULL, ui, 4 * k + i);
        float jre = __shfl_sync(FULL, ur, 4 * k + j);
        float jim = __shfl_sync(FULL, ui, 4 * k + j);
        float dot = ire * jre + iim * jim;
        acc += (k < 2) ? dot : -dot;
    }
    if (L < 16) sA[L] = fc_w[0] * acc;
    __syncwarp();

    if (L == 0) {
        float A00 = sA[0],  A01 = sA[1],  A02 = sA[2],  A03 = sA[3];
        float A11 = sA[5],  A12 = sA[6],  A13 = sA[7];
        float A22 = sA[10], A23 = sA[11], A33 = sA[15];
        sK[0] = 0.25f * (A00 + A11 + A22 + A33) + fc_b[0];
        sK[1] = 0.25f * (A00 - A11 + A22 - A33);   // C1
        sK[2] = 0.50f * (A01 + A23);               // S1
        sK[3] = 0.25f * (A00 + A11 - A22 - A33);   // C0
        sK[4] = 0.25f * (A00 - A11 - A22 + A33);   // C0C1
        sK[5] = 0.50f * (A01 - A23);               // C0S1
        sK[6] = 0.50f * (A02 + A13);               // S0
        sK[7] = 0.50f * (A02 - A13);               // S0C1
        sK[8] = 0.50f * (A03 + A12);               // S0S1
    }
}

// 8 samples per thread: 4 input float4, 2 output float4. Single wave.
__global__ void __launch_bounds__(256, 6)
qnn_fused_kernel(const float* __restrict__ qp,
                 const float* __restrict__ fc_w,
                 const float* __restrict__ fc_b,
                 const float4* __restrict__ x4,
                 float4* __restrict__ out4) {
    __shared__ float sA[16];
    __shared__ float sK[9];
    unsigned t = blockIdx.x * 256u + threadIdx.x;

    // Front-batch all global loads: in flight while warp 0 builds K.
    float4 xv0 = __ldcs(&x4[4u * t + 0]);
    float4 xv1 = __ldcs(&x4[4u * t + 1]);
    float4 xv2 = __ldcs(&x4[4u * t + 2]);
    float4 xv3 = __ldcs(&x4[4u * t + 3]);

    if (threadIdx.x < 32) {
        warp_compute_K(qp, fc_w, fc_b, sA, sK);
    }
    __syncthreads();

    float k00 = sK[0], k01 = sK[1], k02 = sK[2];
    float k10 = sK[3], k11 = sK[4], k12 = sK[5];
    float k20 = sK[6], k21 = sK[7], k22 = sK[8];

    float xs[16] = { xv0.x, xv0.y, xv0.z, xv0.w,
                     xv1.x, xv1.y, xv1.z, xv1.w,
                     xv2.x, xv2.y, xv2.z, xv2.w,
                     xv3.x, xv3.y, xv3.z, xv3.w };

    float res[8];
    #pragma unroll
    for (int s = 0; s < 8; s++) {
        float C0, S0, C1, S1;
        __sincosf(xs[2 * s + 0], &S0, &C0);
        __sincosf(xs[2 * s + 1], &S1, &C1);
        float row0 = k00 + k01 * C1 + k02 * S1;
        float row1 = k10 + k11 * C1 + k12 * S1;
        float row2 = k20 + k21 * C1 + k22 * S1;
        res[s] = row0 + C0 * row1 + S0 * row2;
    }

    __stcs(&out4[2u * t + 0], make_float4(res[0], res[1], res[2], res[3]));
    __stcs(&out4[2u * t + 1], make_float4(res[4], res[5], res[6], res[7]));
}

extern "C" void kernel_launch(void* const* d_in, const int* in_sizes, int n_in,
                              void* d_out, int out_size) {
    const float* x    = (const float*)d_in[0];   // [B, 2]
    const float* qp   = (const float*)d_in[1];   // [2, 2, 3]
    const float* fc_w = (const float*)d_in[2];   // [1, 1]
    const float* fc_b = (const float*)d_in[3];   // [1]

    // out_size = B. 8 samples per thread, 256 threads per block -> 1024 blocks.
    int threads = 256;
    int blocks = (out_size + threads * 8 - 1) / (threads * 8);
    qnn_fused_kernel<<<blocks, threads>>>(qp, fc_w, fc_b,
                                          (const float4*)x, (float4*)d_out);
    (void)n_in; (void)in_sizes;
}